// round 16
// baseline (speedup 1.0000x reference)
#include <cuda_runtime.h>
#include <cuda_bf16.h>
#include <math.h>

// Problem constants (fixed by setup_inputs)
#define NF   1024
#define NN   2048
#define DIM  64
#define K12  768
#define NFEAT 256
#define EPS_F 1e-6f
#define LN_EPS_F 1e-5f

#define GRID 128       // all co-resident (<=148 SMs) -> safe grid barrier
#define TPB  1024
#define NPB  16        // nodes per block
#define LCAP 256       // edge-list capacity per node (max degree ~95 here)

#define FT_STRIDE 20   // featT row stride (16B-aligned float4/ull2 reads)
#define WT_STRIDE 65   // wT row stride (65 mod 32 = 1 -> conflict-free both ways)

// Dynamic smem layout (float offsets)
#define WT_OFF     0                           // wT[768][65]     199680 B
#define FEATT_OFF  49920                       // featT[256][20]   20480 B
#define SLIST_OFF  55040                       // 16*256 ushort     8192 B (2048 floats)
#define DYN_FLOATS 57088
#define DYN_BYTES  (DYN_FLOATS * 4)            // 228352 B
// sPart[4][16][3][64] (12288 floats) aliases wT[0:12288] after GEMM completes.

// Device scratch (no allocations allowed)
__device__ float g_bsumT[32 * GRID];      // [slot][block] partial sums
__device__ float g_bcntT[32 * GRID];      // [slot][block] partial counts

// Grid barrier (sense-reversal; state persists across graph replays)
__device__ int                   g_bar_cnt;
__device__ volatile unsigned int g_bar_gen;

// ---- packed fp32x2 helpers (FFMA2 is PTX-only) ----
typedef unsigned long long ull;
__device__ __forceinline__ ull pack2(float lo, float hi) {
    ull r;
    asm("mov.b64 %0, {%1, %2};" : "=l"(r) : "f"(lo), "f"(hi));
    return r;
}
__device__ __forceinline__ void unpack2(ull v, float& lo, float& hi) {
    asm("mov.b64 {%0, %1}, %2;" : "=f"(lo), "=f"(hi) : "l"(v));
}
__device__ __forceinline__ void fma2(ull& d, ull a, ull b) {
    asm("fma.rn.f32x2 %0, %1, %2, %0;" : "+l"(d) : "l"(a), "l"(b));
}

__global__ void __launch_bounds__(TPB, 1)
fused_all(const float* __restrict__ A,
          const float* __restrict__ x,
          const float* __restrict__ W,
          const float* __restrict__ bias,
          const float* __restrict__ gamma,
          const float* __restrict__ beta,
          const int*   __restrict__ b_n,
          float* __restrict__ out) {
    extern __shared__ float sm[];
    float*          wT    = sm + WT_OFF;
    float*          featT = sm + FEATT_OFF;
    unsigned short* sList = (unsigned short*)(sm + SLIST_OFF);
    float*          sPart = sm;                  // aliases wT after GEMM

    __shared__ unsigned int sMask[NPB * 32];
    __shared__ float sLd[NPB], sMs[32], sSc[NPB], sInv[NPB];
    __shared__ int   sBn[NPB], sCnt[NPB];
    __shared__ float sBias[DIM], sGam[DIM], sBet[DIM];
    __shared__ unsigned int sGen;

    const int t   = threadIdx.x;
    const int blk = blockIdx.x;
    const int nb  = blk * NPB;

    // ---- W transpose-load, FIRST HALF: gmem (64,768) -> smem wT[k][65] -----
    // LDG lanes span k (coalesced 128B); STS stride 65 -> conflict-free.
    {
        int wid = t >> 5, l = t & 31;
#pragma unroll 8
        for (int task = wid; task < 768; task += 32) {
            int d  = task / 24;
            int kb = (task - d * 24) * 32;
            wT[(kb + l) * WT_STRIDE + d] = W[d * K12 + kb + l];
        }
    }

    // ---- epilogue params ----
    if (t < NPB) sBn[t] = b_n[nb + t];
    if (t >= 64 && t < 128)  sBias[t - 64]  = bias[t - 64];
    if (t >= 128 && t < 192) sGam[t - 128]  = gamma[t - 128];
    if (t >= 192 && t < 256) sBet[t - 192]  = beta[t - 192];

    // ---- masks straight from L2: thread (w, nl), 32 independent LDGs ----
    if (t < 512) {
        int w  = t >> 4;                       // feature word 0..31
        int nl = t & 15;
        unsigned m = 0;
#pragma unroll
        for (int r = 0; r < 32; r++) {
            if (A[(w * 32 + r) * NN + nb + nl] != 0.0f) m |= (1u << r);
        }
        sMask[nl * 32 + w] = m;
    }
    __syncthreads();

    // ---- edge lists (warp scan, deterministic): warp w (<16) -> node w ----
    if (t < 512) {
        int sub = t >> 5;                      // node 0..15
        int l   = t & 31;
        unsigned m = sMask[sub * 32 + l];
        int c = __popc(m);
        int pre = c;
#pragma unroll
        for (int sh = 1; sh < 32; sh <<= 1) {
            int v = __shfl_up_sync(0xffffffffu, pre, sh);
            if (l >= sh) pre += v;
        }
        pre -= c;
        if (l == 31) sCnt[sub] = pre + c;
        int base = l * 32;
        int pos = pre;
        while (m) {
            int b = __ffs(m) - 1;
            m &= m - 1;
            if (pos < LCAP) sList[sub * LCAP + pos] = (unsigned short)(base + b);
            pos++;
        }
    }
    __syncthreads();

    if (t < NPB) sLd[t] = logf((float)sCnt[t] + 1.0f);
    __syncthreads();

    // per-block batch partials (plain stores; deterministic)
    if (t < 32) {
        float s = 0.0f, c = 0.0f;
#pragma unroll
        for (int nl = 0; nl < NPB; nl++) {
            if (sBn[nl] == t) { s += sLd[nl]; c += 1.0f; }
        }
        g_bsumT[t * GRID + blk] = s;
        g_bcntT[t * GRID + blk] = c;
        __threadfence();                       // publish before arrival
    }

    // ---- ARRIVE (WAIT deferred until after the GEMM) ----
    __syncthreads();
    if (t == 0) {
        unsigned int gen = g_bar_gen;
        sGen = gen;
        if (atomicAdd(&g_bar_cnt, 1) == GRID - 1) {
            g_bar_cnt = 0;
            __threadfence();
            g_bar_gen = gen + 1;
        }
    }

    // ---- W transpose-load, SECOND HALF (latency overlaps the gather) ----
    {
        int wid = t >> 5, l = t & 31;
#pragma unroll 8
        for (int task = 768 + wid; task < 1536; task += 32) {
            int d  = task / 24;
            int kb = (task - d * 24) * 32;
            wT[(kb + l) * WT_STRIDE + d] = W[d * K12 + kb + l];
        }
    }

    // ---- Phase B: x-gather stats, TWO warps per node, scalar d/lane ----
    {
        int wrp  = t >> 5;                     // warp 0..31
        int sub  = wrp >> 1;                   // node 0..15
        int half = wrp & 1;
        int l    = t & 31;
        int dd   = l + half * 32;              // this thread's d

        int cnt  = sCnt[sub];
        int cnt2 = cnt < LCAP ? cnt : LCAP;
        const unsigned short* lst = sList + sub * LCAP;

        float s0 = 0.f, sq0 = 0.f, mn0 = INFINITY, mx0 = -INFINITY;
        int j = 0;
        for (; j + 8 <= cnt2; j += 8) {
            uint4 v = *reinterpret_cast<const uint4*>(lst + j);
            int f0 = v.x & 0xffff, f1 = v.x >> 16;
            int f2 = v.y & 0xffff, f3 = v.y >> 16;
            int f4 = v.z & 0xffff, f5 = v.z >> 16;
            int f6 = v.w & 0xffff, f7 = v.w >> 16;
            float a0 = x[f0 * DIM + dd], a1 = x[f1 * DIM + dd];
            float a2 = x[f2 * DIM + dd], a3 = x[f3 * DIM + dd];
            float a4 = x[f4 * DIM + dd], a5 = x[f5 * DIM + dd];
            float a6 = x[f6 * DIM + dd], a7 = x[f7 * DIM + dd];
            s0  += ((a0 + a1) + (a2 + a3)) + ((a4 + a5) + (a6 + a7));
            sq0 += ((a0 * a0 + a1 * a1) + (a2 * a2 + a3 * a3))
                 + ((a4 * a4 + a5 * a5) + (a6 * a6 + a7 * a7));
            mn0 = fminf(mn0, fminf(fminf(fminf(a0, a1), fminf(a2, a3)),
                                   fminf(fminf(a4, a5), fminf(a6, a7))));
            mx0 = fmaxf(mx0, fmaxf(fmaxf(fmaxf(a0, a1), fmaxf(a2, a3)),
                                   fmaxf(fmaxf(a4, a5), fmaxf(a6, a7))));
        }
        for (; j < cnt2; j++) {
            int f = lst[j];
            float av = x[f * DIM + dd];
            s0 += av; sq0 += av * av;
            mn0 = fminf(mn0, av); mx0 = fmaxf(mx0, av);
        }

        float deg   = (float)cnt + 1.0f;
        float mean0 = s0 / deg;
        float sd0   = sqrtf(fmaxf(sq0 / deg - mean0 * mean0, EPS_F));

        featT[(           dd) * FT_STRIDE + sub] = mean0;
        featT[( DIM     + dd) * FT_STRIDE + sub] = mn0;
        featT[(2 * DIM  + dd) * FT_STRIDE + sub] = mx0;
        featT[(3 * DIM  + dd) * FT_STRIDE + sub] = sd0;
    }
    __syncthreads();   // featT + wT complete -> GEMM

    // ---- Phase C: flat split-K x4 GEMM, 4 nodes/thread, all-smem ----
    // f operands loaded as ulonglong2 (node pairs ARE the f32x2 lanes)
    const int q = t >> 8;           // K-part 0..3 (64 i-rows each)
    const int r = t & 255;
    const int g = r >> 6;           // node quad 0..3
    const int d = r & 63;

    ull a0[2] = {0ull, 0ull};
    ull a1[2] = {0ull, 0ull};
    ull a2[2] = {0ull, 0ull};

    {
        const float* wQ = wT + (q * 192) * WT_STRIDE + d;
        const float* fQ = featT + (q * 64) * FT_STRIDE + g * 4;
#pragma unroll 8
        for (int il = 0; il < 64; il++) {
            const float* wr = wQ + il * (3 * WT_STRIDE);
            float w0s = wr[0];
            float w1s = wr[WT_STRIDE];
            float w2s = wr[2 * WT_STRIDE];
            ull w0 = pack2(w0s, w0s);
            ull w1 = pack2(w1s, w1s);
            ull w2 = pack2(w2s, w2s);
            const float* fp = fQ + il * FT_STRIDE;
            ulonglong2 fa = *reinterpret_cast<const ulonglong2*>(fp);
            fma2(a0[0], fa.x, w0);
            fma2(a1[0], fa.x, w1);
            fma2(a2[0], fa.x, w2);
            fma2(a0[1], fa.y, w0);
            fma2(a1[1], fa.y, w1);
            fma2(a2[1], fa.y, w2);
        }
    }
    __syncthreads();   // all wT reads done -> sPart may alias it

    // write split-K partials: sPart[q][nl][3][64]
    {
        float* myP = sPart + q * (NPB * 3 * DIM);
#pragma unroll
        for (int pr = 0; pr < 2; pr++) {
            float v0lo, v0hi, v1lo, v1hi, v2lo, v2hi;
            unpack2(a0[pr], v0lo, v0hi);
            unpack2(a1[pr], v1lo, v1hi);
            unpack2(a2[pr], v2lo, v2hi);
            int nl = g * 4 + pr * 2;
            myP[((nl    ) * 3 + 0) * DIM + d] = v0lo;
            myP[((nl    ) * 3 + 1) * DIM + d] = v1lo;
            myP[((nl    ) * 3 + 2) * DIM + d] = v2lo;
            myP[((nl + 1) * 3 + 0) * DIM + d] = v0hi;
            myP[((nl + 1) * 3 + 1) * DIM + d] = v1hi;
            myP[((nl + 1) * 3 + 2) * DIM + d] = v2hi;
        }
    }

    // ---- WAIT (skew fully hidden behind gather+GEMM) ----
    if (t == 0) {
        while (g_bar_gen == sGen) { }
    }
    __syncthreads();
    __threadfence();

    // batch reduction: warp w reduces slot w (32 warps, 32 slots)
    {
        int slot = t >> 5;
        int l    = t & 31;
        float s = 0.0f, c = 0.0f;
#pragma unroll
        for (int rr = 0; rr < GRID / 32; rr++) {
            int b = l + rr * 32;
            s += g_bsumT[slot * GRID + b];
            c += g_bcntT[slot * GRID + b];
        }
#pragma unroll
        for (int off = 16; off > 0; off >>= 1) {
            s += __shfl_xor_sync(0xffffffffu, s, off);
            c += __shfl_xor_sync(0xffffffffu, c, off);
        }
        if (l == 0) sMs[slot] = s / fmaxf(c, EPS_F);
    }
    __syncthreads();
    if (t < NPB) {
        float ms = sMs[sBn[t]];
        float sc = sLd[t] / fmaxf(ms, EPS_F);
        sSc[t]  = sc;
        sInv[t] = 1.0f / fmaxf(sc, EPS_F);
    }
    __syncthreads();

    // epilogue: warp w (<16) handles node w; lane l covers d = l and l+32
    if (t < 512) {
        int nl = t >> 5;
        int l  = t & 31;
        int n  = nb + nl;
        float sc  = sSc[nl];
        float inv = sInv[nl];

        float h[2];
#pragma unroll
        for (int u = 0; u < 2; u++) {
            int dd = l + u * 32;
            float c0 = 0.f, c1 = 0.f, c2 = 0.f;
#pragma unroll
            for (int qq = 0; qq < 4; qq++) {
                const float* p = sPart + qq * (NPB * 3 * DIM) + nl * 3 * DIM;
                c0 += p[0 * DIM + dd];
                c1 += p[1 * DIM + dd];
                c2 += p[2 * DIM + dd];
            }
            h[u] = c0 + sc * c1 + inv * c2 + sBias[dd];
        }

        float s1 = h[0] + h[1];
        float s2 = h[0] * h[0] + h[1] * h[1];
#pragma unroll
        for (int off = 16; off > 0; off >>= 1) {
            s1 += __shfl_xor_sync(0xffffffffu, s1, off);
            s2 += __shfl_xor_sync(0xffffffffu, s2, off);
        }
        float mu  = s1 * (1.0f / DIM);
        float var = s2 * (1.0f / DIM) - mu * mu;
        float rs  = rsqrtf(var + LN_EPS_F);
#pragma unroll
        for (int u = 0; u < 2; u++) {
            int dd = l + u * 32;
            float o = (h[u] - mu) * rs * sGam[dd] + sBet[dd];
            out[n * DIM + dd] = fmaxf(o, 0.0f);
        }
    }
}

// ---------------------------------------------------------------------------
extern "C" void kernel_launch(void* const* d_in, const int* in_sizes, int n_in,
                              void* d_out, int out_size) {
    const float* A     = (const float*)d_in[0];   // (1024, 2048)
    const float* x     = (const float*)d_in[1];   // (1024, 64)
    const float* W     = (const float*)d_in[2];   // (64, 768)
    const float* bias  = (const float*)d_in[3];   // (64)
    const float* gamma = (const float*)d_in[4];   // (64)
    const float* beta  = (const float*)d_in[5];   // (64)
    const int*   b_n   = (const int*)d_in[6];     // (2048)
    float* out = (float*)d_out;                   // (2048, 64)

    cudaFuncSetAttribute(fused_all, cudaFuncAttributeMaxDynamicSharedMemorySize, DYN_BYTES);
    fused_all<<<GRID, TPB, DYN_BYTES>>>(A, x, W, bias, gamma, beta, b_n, out);
}

// round 17
// speedup vs baseline: 1.0962x; 1.0962x over previous
#include <cuda_runtime.h>
#include <cuda_bf16.h>
#include <math.h>

// Problem constants (fixed by setup_inputs)
#define NF   1024
#define NN   2048
#define DIM  64
#define K12  768
#define NFEAT 256
#define EPS_F 1e-6f
#define LN_EPS_F 1e-5f

#define GRID 128       // all co-resident (<=148 SMs) -> safe grid barrier
#define TPB  512
#define NPB  16        // nodes per block
#define LCAP 256       // edge-list capacity per node (max degree ~95 here)

#define FT_STRIDE 20   // featT row stride (16B-aligned float4/ull2 reads)
#define WT_STRIDE 65   // wT row stride (65 mod 32 = 1 -> conflict-free both ways)

// Dynamic smem layout (float offsets)
#define WT_OFF     0                           // wT[768][65]     199680 B
#define FEATT_OFF  49920                       // featT[256][20]   20480 B
#define SLIST_OFF  55040                       // 16*256 ushort     8192 B (2048 floats)
#define DYN_FLOATS 57088
#define DYN_BYTES  (DYN_FLOATS * 4)            // 228352 B
// sPart[4][16][3][64] (12288 floats) aliases wT[0:12288] after GEMM completes.

// Device scratch (no allocations allowed)
__device__ float g_bsumT[32 * GRID];      // [slot][block] partial sums
__device__ float g_bcntT[32 * GRID];      // [slot][block] partial counts

// Grid barrier (sense-reversal; state persists across graph replays)
__device__ int                   g_bar_cnt;
__device__ volatile unsigned int g_bar_gen;

// ---- packed fp32x2 helpers (FFMA2 is PTX-only) ----
typedef unsigned long long ull;
__device__ __forceinline__ ull pack2(float lo, float hi) {
    ull r;
    asm("mov.b64 %0, {%1, %2};" : "=l"(r) : "f"(lo), "f"(hi));
    return r;
}
__device__ __forceinline__ void unpack2(ull v, float& lo, float& hi) {
    asm("mov.b64 {%0, %1}, %2;" : "=f"(lo), "=f"(hi) : "l"(v));
}
__device__ __forceinline__ void fma2(ull& d, ull a, ull b) {
    asm("fma.rn.f32x2 %0, %1, %2, %0;" : "+l"(d) : "l"(a), "l"(b));
}

__global__ void __launch_bounds__(TPB, 1)
fused_all(const float* __restrict__ A,
          const float* __restrict__ x,
          const float* __restrict__ W,
          const float* __restrict__ bias,
          const float* __restrict__ gamma,
          const float* __restrict__ beta,
          const int*   __restrict__ b_n,
          float* __restrict__ out) {
    extern __shared__ float sm[];
    float*          wT    = sm + WT_OFF;
    float*          featT = sm + FEATT_OFF;
    unsigned short* sList = (unsigned short*)(sm + SLIST_OFF);
    float*          sPart = sm;                  // aliases wT after GEMM

    __shared__ unsigned int sMask[NPB * 32];
    __shared__ float sLd[NPB], sMs[32], sSc[NPB], sInv[NPB];
    __shared__ int   sBn[NPB], sCnt[NPB];
    __shared__ float sBias[DIM], sGam[DIM], sBet[DIM];
    __shared__ unsigned int sGen;

    const int t   = threadIdx.x;
    const int blk = blockIdx.x;
    const int nb  = blk * NPB;

    // ---- zero masks (atomicOr accumulates into them) ----
    sMask[t] = 0;                               // TPB == NPB*32 == 512

    // ---- W transpose-load, FIRST HALF: gmem (64,768) -> smem wT[k][65] -----
    // LDG lanes span k (coalesced 128B); STS stride 65 -> conflict-free.
    // Second half is issued after the ARRIVE (overlaps the gather phase).
    {
        int wid = t >> 5, l = t & 31;
#pragma unroll 8
        for (int task = wid; task < 768; task += 16) {
            int d  = task / 24;
            int kb = (task - d * 24) * 32;
            wT[(kb + l) * WT_STRIDE + d] = W[d * K12 + kb + l];
        }
    }

    // ---- epilogue params ----
    if (t < NPB) sBn[t] = b_n[nb + t];
    if (t >= 64 && t < 128)  sBias[t - 64]  = bias[t - 64];
    if (t >= 128 && t < 192) sGam[t - 128]  = gamma[t - 128];
    if (t >= 192 && t < 256) sBet[t - 192]  = beta[t - 192];
    __syncthreads();                            // masks zeroed before atomicOr

    // ---- masks via float4 loads + predicated shared atomicOr (5% density) ----
    {
        const float4* A4 = reinterpret_cast<const float4*>(A);
        int nb4 = nb >> 2;
#pragma unroll
        for (int i = 0; i < 8; i++) {
            int idx = i * TPB + t;              // [0, 4096)
            int f   = idx >> 2;                 // feature row
            int c4  = idx & 3;                  // node quad
            float4 p = A4[f * (NN / 4) + nb4 + c4];
            int w = f >> 5;
            unsigned bit = 1u << (f & 31);
            int nl = c4 * 4;
            if (p.x != 0.0f) atomicOr(&sMask[(nl + 0) * 32 + w], bit);
            if (p.y != 0.0f) atomicOr(&sMask[(nl + 1) * 32 + w], bit);
            if (p.z != 0.0f) atomicOr(&sMask[(nl + 2) * 32 + w], bit);
            if (p.w != 0.0f) atomicOr(&sMask[(nl + 3) * 32 + w], bit);
        }
    }
    __syncthreads();

    // ---- edge lists (warp scan, deterministic): warp w -> node w ----
    {
        int sub = t >> 5;                      // node 0..15
        int l   = t & 31;
        unsigned m = sMask[sub * 32 + l];
        int c = __popc(m);
        int pre = c;
#pragma unroll
        for (int sh = 1; sh < 32; sh <<= 1) {
            int v = __shfl_up_sync(0xffffffffu, pre, sh);
            if (l >= sh) pre += v;
        }
        pre -= c;
        if (l == 31) sCnt[sub] = pre + c;
        int base = l * 32;
        int pos = pre;
        while (m) {
            int b = __ffs(m) - 1;
            m &= m - 1;
            if (pos < LCAP) sList[sub * LCAP + pos] = (unsigned short)(base + b);
            pos++;
        }
    }
    __syncthreads();

    if (t < NPB) sLd[t] = logf((float)sCnt[t] + 1.0f);
    __syncthreads();

    // per-block batch partials (plain stores; deterministic)
    if (t < 32) {
        float s = 0.0f, c = 0.0f;
#pragma unroll
        for (int nl = 0; nl < NPB; nl++) {
            if (sBn[nl] == t) { s += sLd[nl]; c += 1.0f; }
        }
        g_bsumT[t * GRID + blk] = s;
        g_bcntT[t * GRID + blk] = c;
        __threadfence();                       // publish before arrival
    }

    // ---- ARRIVE (WAIT deferred until after the GEMM) ----
    __syncthreads();
    if (t == 0) {
        unsigned int gen = g_bar_gen;
        sGen = gen;
        if (atomicAdd(&g_bar_cnt, 1) == GRID - 1) {
            g_bar_cnt = 0;
            __threadfence();
            g_bar_gen = gen + 1;
        }
    }

    // ---- W transpose-load, SECOND HALF (latency overlaps the gather) ----
    {
        int wid = t >> 5, l = t & 31;
#pragma unroll 8
        for (int task = 768 + wid; task < 1536; task += 16) {
            int d  = task / 24;
            int kb = (task - d * 24) * 32;
            wT[(kb + l) * WT_STRIDE + d] = W[d * K12 + kb + l];
        }
    }

    // ---- Phase B: x-gather stats, warp per node, d = 2l, 2l+1 (float2) ----
    {
        int sub = t >> 5;                      // node 0..15
        int l   = t & 31;                      // d = 2l (x) and 2l+1 (y)
        int cnt  = sCnt[sub];
        int cnt2 = cnt < LCAP ? cnt : LCAP;
        const unsigned short* lst = sList + sub * LCAP;
        const float2* x2 = reinterpret_cast<const float2*>(x);  // [f*32 + l]

        float s0 = 0.f, sq0 = 0.f, mn0 = INFINITY, mx0 = -INFINITY;
        float s1 = 0.f, sq1 = 0.f, mn1 = INFINITY, mx1 = -INFINITY;
        int j = 0;
        for (; j + 8 <= cnt2; j += 8) {
            uint4 v = *reinterpret_cast<const uint4*>(lst + j);
            int f0 = v.x & 0xffff, f1 = v.x >> 16;
            int f2 = v.y & 0xffff, f3 = v.y >> 16;
            int f4 = v.z & 0xffff, f5 = v.z >> 16;
            int f6 = v.w & 0xffff, f7 = v.w >> 16;
            float2 p0 = x2[f0 * 32 + l];
            float2 p1 = x2[f1 * 32 + l];
            float2 p2 = x2[f2 * 32 + l];
            float2 p3 = x2[f3 * 32 + l];
            float2 p4 = x2[f4 * 32 + l];
            float2 p5 = x2[f5 * 32 + l];
            float2 p6 = x2[f6 * 32 + l];
            float2 p7 = x2[f7 * 32 + l];
            s0  += ((p0.x + p1.x) + (p2.x + p3.x)) + ((p4.x + p5.x) + (p6.x + p7.x));
            sq0 += ((p0.x * p0.x + p1.x * p1.x) + (p2.x * p2.x + p3.x * p3.x))
                 + ((p4.x * p4.x + p5.x * p5.x) + (p6.x * p6.x + p7.x * p7.x));
            mn0 = fminf(mn0, fminf(fminf(fminf(p0.x, p1.x), fminf(p2.x, p3.x)),
                                   fminf(fminf(p4.x, p5.x), fminf(p6.x, p7.x))));
            mx0 = fmaxf(mx0, fmaxf(fmaxf(fmaxf(p0.x, p1.x), fmaxf(p2.x, p3.x)),
                                   fmaxf(fmaxf(p4.x, p5.x), fmaxf(p6.x, p7.x))));
            s1  += ((p0.y + p1.y) + (p2.y + p3.y)) + ((p4.y + p5.y) + (p6.y + p7.y));
            sq1 += ((p0.y * p0.y + p1.y * p1.y) + (p2.y * p2.y + p3.y * p3.y))
                 + ((p4.y * p4.y + p5.y * p5.y) + (p6.y * p6.y + p7.y * p7.y));
            mn1 = fminf(mn1, fminf(fminf(fminf(p0.y, p1.y), fminf(p2.y, p3.y)),
                                   fminf(fminf(p4.y, p5.y), fminf(p6.y, p7.y))));
            mx1 = fmaxf(mx1, fmaxf(fmaxf(fmaxf(p0.y, p1.y), fmaxf(p2.y, p3.y)),
                                   fmaxf(fmaxf(p4.y, p5.y), fmaxf(p6.y, p7.y))));
        }
        for (; j < cnt2; j++) {
            int f = lst[j];
            float2 p = x2[f * 32 + l];
            s0 += p.x; sq0 += p.x * p.x; mn0 = fminf(mn0, p.x); mx0 = fmaxf(mx0, p.x);
            s1 += p.y; sq1 += p.y * p.y; mn1 = fminf(mn1, p.y); mx1 = fmaxf(mx1, p.y);
        }

        float deg = (float)cnt + 1.0f;
        float mean0 = s0 / deg, mean1 = s1 / deg;
        float sd0 = sqrtf(fmaxf(sq0 / deg - mean0 * mean0, EPS_F));
        float sd1 = sqrtf(fmaxf(sq1 / deg - mean1 * mean1, EPS_F));

        int d0 = 2 * l, d1 = 2 * l + 1;
        featT[(           d0) * FT_STRIDE + sub] = mean0;
        featT[( DIM     + d0) * FT_STRIDE + sub] = mn0;
        featT[(2 * DIM  + d0) * FT_STRIDE + sub] = mx0;
        featT[(3 * DIM  + d0) * FT_STRIDE + sub] = sd0;
        featT[(           d1) * FT_STRIDE + sub] = mean1;
        featT[( DIM     + d1) * FT_STRIDE + sub] = mn1;
        featT[(2 * DIM  + d1) * FT_STRIDE + sub] = mx1;
        featT[(3 * DIM  + d1) * FT_STRIDE + sub] = sd1;
    }
    __syncthreads();   // featT + wT complete -> GEMM

    // ---- Phase C: flat split-K x4 GEMM, 8 nodes/thread, all-smem ----
    // f operands loaded as ulonglong2 (node pairs ARE the f32x2 lanes; no packs)
    const int q = t >> 7;           // K-part 0..3 (64 i-rows each)
    const int r = t & 127;
    const int g = r >> 6;           // node octet 0..1
    const int d = r & 63;

    ull a0[4] = {0ull, 0ull, 0ull, 0ull};
    ull a1[4] = {0ull, 0ull, 0ull, 0ull};
    ull a2[4] = {0ull, 0ull, 0ull, 0ull};

    {
        const float* wQ = wT + (q * 192) * WT_STRIDE + d;
        const float* fQ = featT + (q * 64) * FT_STRIDE + g * 8;
#pragma unroll 8
        for (int il = 0; il < 64; il++) {
            const float* wr = wQ + il * (3 * WT_STRIDE);
            float w0s = wr[0];
            float w1s = wr[WT_STRIDE];
            float w2s = wr[2 * WT_STRIDE];
            ull w0 = pack2(w0s, w0s);
            ull w1 = pack2(w1s, w1s);
            ull w2 = pack2(w2s, w2s);
            const float* fp = fQ + il * FT_STRIDE;
            ulonglong2 fa = *reinterpret_cast<const ulonglong2*>(fp);
            ulonglong2 fb = *reinterpret_cast<const ulonglong2*>(fp + 4);
            fma2(a0[0], fa.x, w0);
            fma2(a1[0], fa.x, w1);
            fma2(a2[0], fa.x, w2);
            fma2(a0[1], fa.y, w0);
            fma2(a1[1], fa.y, w1);
            fma2(a2[1], fa.y, w2);
            fma2(a0[2], fb.x, w0);
            fma2(a1[2], fb.x, w1);
            fma2(a2[2], fb.x, w2);
            fma2(a0[3], fb.y, w0);
            fma2(a1[3], fb.y, w1);
            fma2(a2[3], fb.y, w2);
        }
    }
    __syncthreads();   // all wT reads done -> sPart may alias it

    // write split-K partials: sPart[q][nl][3][64]
    {
        float* myP = sPart + q * (NPB * 3 * DIM);
#pragma unroll
        for (int pr = 0; pr < 4; pr++) {
            float v0lo, v0hi, v1lo, v1hi, v2lo, v2hi;
            unpack2(a0[pr], v0lo, v0hi);
            unpack2(a1[pr], v1lo, v1hi);
            unpack2(a2[pr], v2lo, v2hi);
            int nl = g * 8 + pr * 2;
            myP[((nl    ) * 3 + 0) * DIM + d] = v0lo;
            myP[((nl    ) * 3 + 1) * DIM + d] = v1lo;
            myP[((nl    ) * 3 + 2) * DIM + d] = v2lo;
            myP[((nl + 1) * 3 + 0) * DIM + d] = v0hi;
            myP[((nl + 1) * 3 + 1) * DIM + d] = v1hi;
            myP[((nl + 1) * 3 + 2) * DIM + d] = v2hi;
        }
    }

    // ---- WAIT (skew fully hidden behind gather+GEMM) ----
    if (t == 0) {
        while (g_bar_gen == sGen) { }
    }
    __syncthreads();
    __threadfence();

    // batch reduction: warp w reduces slots w and w+16
    {
        int w0 = t >> 5;
        int l  = t & 31;
#pragma unroll
        for (int hh = 0; hh < 2; hh++) {
            int slot = w0 + hh * 16;
            float s = 0.0f, c = 0.0f;
#pragma unroll
            for (int rr = 0; rr < GRID / 32; rr++) {
                int b = l + rr * 32;
                s += g_bsumT[slot * GRID + b];
                c += g_bcntT[slot * GRID + b];
            }
#pragma unroll
            for (int off = 16; off > 0; off >>= 1) {
                s += __shfl_xor_sync(0xffffffffu, s, off);
                c += __shfl_xor_sync(0xffffffffu, c, off);
            }
            if (l == 0) sMs[slot] = s / fmaxf(c, EPS_F);
        }
    }
    __syncthreads();
    if (t < NPB) {
        float ms = sMs[sBn[t]];
        float sc = sLd[t] / fmaxf(ms, EPS_F);
        sSc[t]  = sc;
        sInv[t] = 1.0f / fmaxf(sc, EPS_F);
    }
    __syncthreads();

    // epilogue: warp w handles node w; lane l covers d = l and l+32
    {
        int nl = t >> 5;
        int l  = t & 31;
        int n  = nb + nl;
        float sc  = sSc[nl];
        float inv = sInv[nl];

        float h[2];
#pragma unroll
        for (int u = 0; u < 2; u++) {
            int dd = l + u * 32;
            float c0 = 0.f, c1 = 0.f, c2 = 0.f;
#pragma unroll
            for (int qq = 0; qq < 4; qq++) {
                const float* p = sPart + qq * (NPB * 3 * DIM) + nl * 3 * DIM;
                c0 += p[0 * DIM + dd];
                c1 += p[1 * DIM + dd];
                c2 += p[2 * DIM + dd];
            }
            h[u] = c0 + sc * c1 + inv * c2 + sBias[dd];
        }

        float s1 = h[0] + h[1];
        float s2 = h[0] * h[0] + h[1] * h[1];
#pragma unroll
        for (int off = 16; off > 0; off >>= 1) {
            s1 += __shfl_xor_sync(0xffffffffu, s1, off);
            s2 += __shfl_xor_sync(0xffffffffu, s2, off);
        }
        float mu  = s1 * (1.0f / DIM);
        float var = s2 * (1.0f / DIM) - mu * mu;
        float rs  = rsqrtf(var + LN_EPS_F);
#pragma unroll
        for (int u = 0; u < 2; u++) {
            int dd = l + u * 32;
            float o = (h[u] - mu) * rs * sGam[dd] + sBet[dd];
            out[n * DIM + dd] = fmaxf(o, 0.0f);
        }
    }
}

// ---------------------------------------------------------------------------
extern "C" void kernel_launch(void* const* d_in, const int* in_sizes, int n_in,
                              void* d_out, int out_size) {
    const float* A     = (const float*)d_in[0];   // (1024, 2048)
    const float* x     = (const float*)d_in[1];   // (1024, 64)
    const float* W     = (const float*)d_in[2];   // (64, 768)
    const float* bias  = (const float*)d_in[3];   // (64)
    const float* gamma = (const float*)d_in[4];   // (64)
    const float* beta  = (const float*)d_in[5];   // (64)
    const int*   b_n   = (const int*)d_in[6];     // (2048)
    float* out = (float*)d_out;                   // (2048, 64)

    cudaFuncSetAttribute(fused_all, cudaFuncAttributeMaxDynamicSharedMemorySize, DYN_BYTES);
    fused_all<<<GRID, TPB, DYN_BYTES>>>(A, x, W, bias, gamma, beta, b_n, out);
}